// round 4
// baseline (speedup 1.0000x reference)
#include <cuda_runtime.h>
#include <cuda_bf16.h>
#include <cstdint>

// ---------------------------------------------------------------------------
// Problem constants
// ---------------------------------------------------------------------------
#define NTOK 8192
#define TOPK 2
#define NEXP 8
#define KDIM 512
#define NDIM 1024
#define MROWS (NTOK * TOPK)   // 16384

// GEMM tiling (mma.sync path — base sm_100 target, no tcgen05 available)
#define TILE_M 128
#define TILE_N 128
#define CH_K   32                 // bf16 K elems per chunk (64 bytes/row)
#define SPLITK 2
#define CH_PER_CTA (KDIM / CH_K / SPLITK)   // 8
// Swizzled smem: row stride 64B, 16B chunk c stored at c ^ ((row>>1)&3)
#define TBYTES (TILE_M * 64)      // 8192 per tensor (A/B tiles are both 128 rows)
#define STAGE  (4 * TBYTES)       // Ah, Al, Bh, Bl = 32768
#define NSTAGE 3
#define SMEM_GEMM (NSTAGE * STAGE)  // 98304

// ---------------------------------------------------------------------------
// PTX helpers (base-target instructions, sm_90 or lower vintage)
// ---------------------------------------------------------------------------
__device__ __forceinline__ uint32_t smem_to_u32(const void* p) {
    uint32_t a;
    asm("{ .reg .u64 t; cvta.to.shared.u64 t, %1; cvt.u32.u64 %0, t; }"
        : "=r"(a) : "l"(p));
    return a;
}

__device__ __forceinline__ void cp_async16(uint32_t dst, const void* src) {
    asm volatile("cp.async.cg.shared.global [%0], [%1], 16;"
                 :: "r"(dst), "l"(src) : "memory");
}
__device__ __forceinline__ void cp_commit() {
    asm volatile("cp.async.commit_group;" ::: "memory");
}
template <int N>
__device__ __forceinline__ void cp_wait() {
    asm volatile("cp.async.wait_group %0;" :: "n"(N) : "memory");
}

__device__ __forceinline__ void ldm_x4(uint32_t* r, uint32_t addr) {
    asm volatile("ldmatrix.sync.aligned.m8n8.x4.shared.b16 {%0,%1,%2,%3}, [%4];"
                 : "=r"(r[0]), "=r"(r[1]), "=r"(r[2]), "=r"(r[3])
                 : "r"(addr));
}

__device__ __forceinline__ void mma_bf16(float* c, const uint32_t* a,
                                         const uint32_t* b) {
    asm volatile(
        "mma.sync.aligned.m16n8k16.row.col.f32.bf16.bf16.f32 "
        "{%0,%1,%2,%3}, {%4,%5,%6,%7}, {%8,%9}, {%0,%1,%2,%3};"
        : "+f"(c[0]), "+f"(c[1]), "+f"(c[2]), "+f"(c[3])
        : "r"(a[0]), "r"(a[1]), "r"(a[2]), "r"(a[3]), "r"(b[0]), "r"(b[1]));
}

__device__ __forceinline__ void red_add_v2(float* gaddr, float x, float y) {
    asm volatile("red.global.add.v2.f32 [%0], {%1, %2};"
                 :: "l"(gaddr), "f"(x), "f"(y) : "memory");
}

// ---------------------------------------------------------------------------
// Scratch (static __device__ — no allocation allowed)
// ---------------------------------------------------------------------------
__device__ uint4  d_a_hi4[MROWS * KDIM / 8];          // bf16 [M,K] hi (16 MB)
__device__ uint4  d_a_lo4[MROWS * KDIM / 8];          // bf16 [M,K] lo
__device__ uint4  d_w_hi4[NEXP * NDIM * KDIM / 8];    // bf16 [E,N,K] hi (8 MB)
__device__ uint4  d_w_lo4[NEXP * NDIM * KDIM / 8];    // bf16 [E,N,K] lo
__device__ float  d_rowscale[MROWS];
__device__ int    d_inv[MROWS];                       // inv[s] = token of sorted row s

__device__ __forceinline__ void split_bf16(float x, __nv_bfloat16& h, __nv_bfloat16& l) {
    h = __float2bfloat16_rn(x);
    l = __float2bfloat16_rn(x - __bfloat162float(h));
}

// ---------------------------------------------------------------------------
// Kernel 1: split input f32 -> bf16 hi/lo, and zero the output surface
// ---------------------------------------------------------------------------
__global__ void k_split_input(const float4* __restrict__ in4,
                              float4* __restrict__ out4) {
    int i = blockIdx.x * blockDim.x + threadIdx.x;   // exactly MROWS*KDIM/8 threads
    // zero d_out: NTOK*NDIM/4 = 2*nthreads float4s
    out4[2 * i]     = make_float4(0.f, 0.f, 0.f, 0.f);
    out4[2 * i + 1] = make_float4(0.f, 0.f, 0.f, 0.f);

    float4 v0 = in4[2 * i], v1 = in4[2 * i + 1];
    __nv_bfloat16 h[8], l[8];
    split_bf16(v0.x, h[0], l[0]); split_bf16(v0.y, h[1], l[1]);
    split_bf16(v0.z, h[2], l[2]); split_bf16(v0.w, h[3], l[3]);
    split_bf16(v1.x, h[4], l[4]); split_bf16(v1.y, h[5], l[5]);
    split_bf16(v1.z, h[6], l[6]); split_bf16(v1.w, h[7], l[7]);
    uint4 uh, ul;
    __nv_bfloat162 t;
    t = __nv_bfloat162(h[0], h[1]); uh.x = *(uint32_t*)&t;
    t = __nv_bfloat162(h[2], h[3]); uh.y = *(uint32_t*)&t;
    t = __nv_bfloat162(h[4], h[5]); uh.z = *(uint32_t*)&t;
    t = __nv_bfloat162(h[6], h[7]); uh.w = *(uint32_t*)&t;
    t = __nv_bfloat162(l[0], l[1]); ul.x = *(uint32_t*)&t;
    t = __nv_bfloat162(l[2], l[3]); ul.y = *(uint32_t*)&t;
    t = __nv_bfloat162(l[4], l[5]); ul.z = *(uint32_t*)&t;
    t = __nv_bfloat162(l[6], l[7]); ul.w = *(uint32_t*)&t;
    d_a_hi4[i] = uh;
    d_a_lo4[i] = ul;
}

// ---------------------------------------------------------------------------
// Kernel 2: weight [E,K,N] f32 -> [E,N,K] bf16 hi/lo (32x32 SMEM transpose)
// ---------------------------------------------------------------------------
__global__ void k_split_weight(const float* __restrict__ w) {
    __shared__ float tile[32][33];
    int e = blockIdx.z;
    int k0 = blockIdx.x * 32;
    int n0 = blockIdx.y * 32;
    int tx = threadIdx.x, ty = threadIdx.y;   // (32, 8)
    #pragma unroll
    for (int i = 0; i < 4; i++) {
        int k = k0 + ty + 8 * i;
        tile[ty + 8 * i][tx] = w[((size_t)e * KDIM + k) * NDIM + n0 + tx];
    }
    __syncthreads();
    __nv_bfloat16* wh = (__nv_bfloat16*)d_w_hi4;
    __nv_bfloat16* wl = (__nv_bfloat16*)d_w_lo4;
    #pragma unroll
    for (int i = 0; i < 4; i++) {
        int n = n0 + ty + 8 * i;
        float v = tile[tx][ty + 8 * i];       // = w[e][k0+tx][n]
        __nv_bfloat16 h, l;
        split_bf16(v, h, l);
        size_t o = ((size_t)e * NDIM + n) * KDIM + k0 + tx;
        wh[o] = h;
        wl[o] = l;
    }
}

// ---------------------------------------------------------------------------
// Kernel 3: per-row epilogue scale + inverse scatter index
// ---------------------------------------------------------------------------
__global__ void k_small(const int* __restrict__ splits,
                        const int* __restrict__ sidx,
                        const float* __restrict__ is,
                        const float* __restrict__ ws,
                        const float* __restrict__ ovs) {
    int m = blockIdx.x * blockDim.x + threadIdx.x;
    if (m >= MROWS) return;
    int e = 0, cum = splits[0];
    while (m >= cum && e < NEXP - 1) { e++; cum += splits[e]; }
    d_rowscale[m] = is[0] * ws[e] * ovs[m];
    d_inv[sidx[m]] = m / TOPK;     // sidx flat index m = t*TOPK + k
}

// ---------------------------------------------------------------------------
// Kernel 4: grouped GEMM (3-term bf16 mma.sync, 3-stage cp.async, swizzled
// SMEM, split-K x2, fused scale + scatter-reduce epilogue via red.global)
// ---------------------------------------------------------------------------
__device__ __forceinline__ void load_chunk(uint32_t stagebase, int ch,
                                           int tid, int m0, int n0, int e) {
    const char* aH = (const char*)d_a_hi4;
    const char* aL = (const char*)d_a_lo4;
    const char* bH = (const char*)d_w_hi4;
    const char* bL = (const char*)d_w_lo4;
    // 512 16B-chunks per tensor: row = i>>2 (128 rows), c = i&3
    #pragma unroll
    for (int rep = 0; rep < 2; rep++) {
        int i = tid + rep * 256;
        int row = i >> 2, c = i & 3;
        uint32_t soff = row * 64 + ((c ^ ((row >> 1) & 3)) << 4);
        size_t ga = ((size_t)(m0 + row) * KDIM + ch * CH_K) * 2 + c * 16;
        size_t gb = (((size_t)e * NDIM + n0 + row) * KDIM + ch * CH_K) * 2 + c * 16;
        cp_async16(stagebase + 0 * TBYTES + soff, aH + ga);
        cp_async16(stagebase + 1 * TBYTES + soff, aL + ga);
        cp_async16(stagebase + 2 * TBYTES + soff, bH + gb);
        cp_async16(stagebase + 3 * TBYTES + soff, bL + gb);
    }
}

__global__ void __launch_bounds__(256, 2)
k_moe_gemm(const int* __restrict__ splits, float* __restrict__ out) {
    extern __shared__ char smem[];
    uint32_t sbase = smem_to_u32(smem);
    int tid = threadIdx.x;
    int wid = tid >> 5;
    int lid = tid & 31;
    int wm = wid >> 2;        // 0..1  (64-row slab)
    int wn = wid & 3;         // 0..3  (32-col slab)

    int m0 = blockIdx.x * TILE_M;
    int n0 = blockIdx.y * TILE_N;
    int ch0 = blockIdx.z * CH_PER_CTA;       // split-K: this CTA's chunk range

    // expert of this M tile (2048 % 128 == 0: tiles never straddle)
    int e = 0, cum = splits[0];
    while (m0 >= cum && e < NEXP - 1) { e++; cum += splits[e]; }

    // per-thread ldmatrix bases (swizzle term invariant under row += 16)
    int rA = wm * 64 + (lid & 15);          // + mi*16
    int cA = lid >> 4;                      // + 2*ks
    int swA = (rA >> 1) & 3;
    int g = lid >> 3, r = lid & 7;
    int rB = wn * 32 + ((g >> 1) << 3) + r; // + bi*16
    int cB = g & 1;                         // + 2*ks
    int swB = (rB >> 1) & 3;
    uint32_t baseA = (uint32_t)rA * 64;
    uint32_t baseB = (uint32_t)rB * 64;

    float acc[4][4][4];
    #pragma unroll
    for (int mi = 0; mi < 4; mi++)
        #pragma unroll
        for (int ni = 0; ni < 4; ni++)
            #pragma unroll
            for (int q = 0; q < 4; q++) acc[mi][ni][q] = 0.f;

    uint32_t st_c = sbase, st_n = sbase + STAGE, st_p = sbase + 2 * STAGE;
    load_chunk(st_c, ch0 + 0, tid, m0, n0, e); cp_commit();
    load_chunk(st_n, ch0 + 1, tid, m0, n0, e); cp_commit();

    for (int ch = 0; ch < CH_PER_CTA; ch++) {
        cp_wait<1>();
        __syncthreads();      // all warps done reading slot st_p -> safe to fill
        if (ch + 2 < CH_PER_CTA) load_chunk(st_p, ch0 + ch + 2, tid, m0, n0, e);
        cp_commit();          // always commit (keeps pending-group invariant)

        uint32_t Ah = st_c, Al = st_c + TBYTES;
        uint32_t Bh = st_c + 2 * TBYTES, Bl = st_c + 3 * TBYTES;

        #pragma unroll
        for (int ks = 0; ks < 2; ks++) {
            uint32_t coA = (uint32_t)(((cA + 2 * ks) ^ swA) << 4);
            uint32_t coB = (uint32_t)(((cB + 2 * ks) ^ swB) << 4);
            uint32_t ah[4][4], bh[2][4];
            #pragma unroll
            for (int mi = 0; mi < 4; mi++)
                ldm_x4(ah[mi], Ah + baseA + mi * 1024 + coA);
            #pragma unroll
            for (int bi = 0; bi < 2; bi++)
                ldm_x4(bh[bi], Bh + baseB + bi * 1024 + coB);
            #pragma unroll
            for (int mi = 0; mi < 4; mi++)
                #pragma unroll
                for (int ni = 0; ni < 4; ni++)
                    mma_bf16(acc[mi][ni], ah[mi], &bh[ni >> 1][(ni & 1) * 2]);

            uint32_t al[4][4];
            #pragma unroll
            for (int mi = 0; mi < 4; mi++)
                ldm_x4(al[mi], Al + baseA + mi * 1024 + coA);
            #pragma unroll
            for (int mi = 0; mi < 4; mi++)
                #pragma unroll
                for (int ni = 0; ni < 4; ni++)
                    mma_bf16(acc[mi][ni], al[mi], &bh[ni >> 1][(ni & 1) * 2]);

            uint32_t bl[2][4];
            #pragma unroll
            for (int bi = 0; bi < 2; bi++)
                ldm_x4(bl[bi], Bl + baseB + bi * 1024 + coB);
            #pragma unroll
            for (int mi = 0; mi < 4; mi++)
                #pragma unroll
                for (int ni = 0; ni < 4; ni++)
                    mma_bf16(acc[mi][ni], ah[mi], &bl[ni >> 1][(ni & 1) * 2]);
        }
        // rotate stages
        uint32_t tmp = st_c; st_c = st_n; st_n = st_p; st_p = tmp;
    }

    // fused epilogue: out[inv[m]] += acc * rowscale[m]  (scatter-reduce)
    int r0 = m0 + wm * 64 + (lid >> 2);
    int ncol0 = n0 + wn * 32 + (lid & 3) * 2;
    #pragma unroll
    for (int mi = 0; mi < 4; mi++) {
        int ma = r0 + mi * 16, mb = ma + 8;
        int   ta = d_inv[ma],      tb = d_inv[mb];
        float sa = d_rowscale[ma], sb = d_rowscale[mb];
        #pragma unroll
        for (int ni = 0; ni < 4; ni++) {
            int n = ncol0 + ni * 8;
            red_add_v2(&out[(size_t)ta * NDIM + n],
                       acc[mi][ni][0] * sa, acc[mi][ni][1] * sa);
            red_add_v2(&out[(size_t)tb * NDIM + n],
                       acc[mi][ni][2] * sb, acc[mi][ni][3] * sb);
        }
    }
}

// ---------------------------------------------------------------------------
// Launch
// ---------------------------------------------------------------------------
extern "C" void kernel_launch(void* const* d_in, const int* in_sizes, int n_in,
                              void* d_out, int out_size) {
    const float* inp    = (const float*)d_in[0];
    const float* weight = (const float*)d_in[1];
    const int*   splits = (const int*)d_in[2];
    const int*   sidx   = (const int*)d_in[3];
    const float* iscale = (const float*)d_in[4];
    const float* wscale = (const float*)d_in[5];
    const float* ovs    = (const float*)d_in[6];
    float* out = (float*)d_out;

    cudaFuncSetAttribute(k_moe_gemm,
                         cudaFuncAttributeMaxDynamicSharedMemorySize, SMEM_GEMM);

    k_split_input<<<(MROWS * KDIM / 8) / 256, 256>>>((const float4*)inp,
                                                     (float4*)out);
    k_split_weight<<<dim3(KDIM / 32, NDIM / 32, NEXP), dim3(32, 8)>>>(weight);
    k_small<<<(MROWS + 255) / 256, 256>>>(splits, sidx, iscale, wscale, ovs);
    k_moe_gemm<<<dim3(MROWS / TILE_M, NDIM / TILE_N, SPLITK), 256, SMEM_GEMM>>>(
        splits, out);
}

// round 6
// speedup vs baseline: 1.0523x; 1.0523x over previous
#include <cuda_runtime.h>
#include <cuda_bf16.h>
#include <cstdint>

// ---------------------------------------------------------------------------
// Problem constants
// ---------------------------------------------------------------------------
#define NTOK 8192
#define TOPK 2
#define NEXP 8
#define KDIM 512
#define NDIM 1024
#define MROWS (NTOK * TOPK)   // 16384

// GEMM tiling (mma.sync path — base sm_100 target, no tcgen05 available)
#define TILE_M 128
#define TILE_N 128
#define CH_K   32                 // bf16 K elems per chunk (64 bytes/row)
#define NUM_CH (KDIM / CH_K)      // 16
#define NTILES ((MROWS / TILE_M) * (NDIM / TILE_N))   // 1024
#define NTN    (NDIM / TILE_N)    // 8
// Swizzled smem: row stride 64B, 16B chunk c stored at c ^ ((row>>1)&3)
#define TBYTES (TILE_M * 64)      // 8192 per tensor (A/B tiles are both 128 rows)
#define STAGE  (4 * TBYTES)       // Ah, Al, Bh, Bl = 32768
#define NSTAGE 3
#define SMEM_GEMM (NSTAGE * STAGE + 16)  // + broadcast slot
#define GRID_GEMM 296             // 2 persistent CTAs per SM

// ---------------------------------------------------------------------------
// PTX helpers (base-target instructions, sm_90 or lower vintage)
// ---------------------------------------------------------------------------
__device__ __forceinline__ uint32_t smem_to_u32(const void* p) {
    uint32_t a;
    asm("{ .reg .u64 t; cvta.to.shared.u64 t, %1; cvt.u32.u64 %0, t; }"
        : "=r"(a) : "l"(p));
    return a;
}

__device__ __forceinline__ void cp_async16(uint32_t dst, const void* src) {
    asm volatile("cp.async.cg.shared.global [%0], [%1], 16;"
                 :: "r"(dst), "l"(src) : "memory");
}
__device__ __forceinline__ void cp_commit() {
    asm volatile("cp.async.commit_group;" ::: "memory");
}
template <int N>
__device__ __forceinline__ void cp_wait() {
    asm volatile("cp.async.wait_group %0;" :: "n"(N) : "memory");
}

__device__ __forceinline__ void ldm_x4(uint32_t* r, uint32_t addr) {
    asm volatile("ldmatrix.sync.aligned.m8n8.x4.shared.b16 {%0,%1,%2,%3}, [%4];"
                 : "=r"(r[0]), "=r"(r[1]), "=r"(r[2]), "=r"(r[3])
                 : "r"(addr));
}

__device__ __forceinline__ void mma_bf16(float* c, const uint32_t* a,
                                         const uint32_t* b) {
    asm volatile(
        "mma.sync.aligned.m16n8k16.row.col.f32.bf16.bf16.f32 "
        "{%0,%1,%2,%3}, {%4,%5,%6,%7}, {%8,%9}, {%0,%1,%2,%3};"
        : "+f"(c[0]), "+f"(c[1]), "+f"(c[2]), "+f"(c[3])
        : "r"(a[0]), "r"(a[1]), "r"(a[2]), "r"(a[3]), "r"(b[0]), "r"(b[1]));
}

__device__ __forceinline__ void red_add_v2(float* gaddr, float x, float y) {
    asm volatile("red.global.add.v2.f32 [%0], {%1, %2};"
                 :: "l"(gaddr), "f"(x), "f"(y) : "memory");
}

// ---------------------------------------------------------------------------
// Scratch (static __device__ — no allocation allowed)
// ---------------------------------------------------------------------------
__device__ uint4  d_a_hi4[MROWS * KDIM / 8];          // bf16 [M,K] hi (16 MB)
__device__ uint4  d_a_lo4[MROWS * KDIM / 8];          // bf16 [M,K] lo
__device__ uint4  d_w_hi4[NEXP * NDIM * KDIM / 8];    // bf16 [E,N,K] hi (8 MB)
__device__ uint4  d_w_lo4[NEXP * NDIM * KDIM / 8];    // bf16 [E,N,K] lo
__device__ float  d_rowscale[MROWS];
__device__ int    d_inv[MROWS];                       // inv[s] = token of sorted row s
__device__ int    d_tilectr;                          // dynamic tile counter

__device__ __forceinline__ void split_bf16(float x, __nv_bfloat16& h, __nv_bfloat16& l) {
    h = __float2bfloat16_rn(x);
    l = __float2bfloat16_rn(x - __bfloat162float(h));
}

// ---------------------------------------------------------------------------
// Kernel 1: split input f32 -> bf16 hi/lo, and zero the output surface
// ---------------------------------------------------------------------------
__global__ void k_split_input(const float4* __restrict__ in4,
                              float4* __restrict__ out4) {
    int i = blockIdx.x * blockDim.x + threadIdx.x;   // exactly MROWS*KDIM/8 threads
    // zero d_out: NTOK*NDIM/4 = 2*nthreads float4s
    out4[2 * i]     = make_float4(0.f, 0.f, 0.f, 0.f);
    out4[2 * i + 1] = make_float4(0.f, 0.f, 0.f, 0.f);

    float4 v0 = in4[2 * i], v1 = in4[2 * i + 1];
    __nv_bfloat16 h[8], l[8];
    split_bf16(v0.x, h[0], l[0]); split_bf16(v0.y, h[1], l[1]);
    split_bf16(v0.z, h[2], l[2]); split_bf16(v0.w, h[3], l[3]);
    split_bf16(v1.x, h[4], l[4]); split_bf16(v1.y, h[5], l[5]);
    split_bf16(v1.z, h[6], l[6]); split_bf16(v1.w, h[7], l[7]);
    uint4 uh, ul;
    __nv_bfloat162 t;
    t = __nv_bfloat162(h[0], h[1]); uh.x = *(uint32_t*)&t;
    t = __nv_bfloat162(h[2], h[3]); uh.y = *(uint32_t*)&t;
    t = __nv_bfloat162(h[4], h[5]); uh.z = *(uint32_t*)&t;
    t = __nv_bfloat162(h[6], h[7]); uh.w = *(uint32_t*)&t;
    t = __nv_bfloat162(l[0], l[1]); ul.x = *(uint32_t*)&t;
    t = __nv_bfloat162(l[2], l[3]); ul.y = *(uint32_t*)&t;
    t = __nv_bfloat162(l[4], l[5]); ul.z = *(uint32_t*)&t;
    t = __nv_bfloat162(l[6], l[7]); ul.w = *(uint32_t*)&t;
    d_a_hi4[i] = uh;
    d_a_lo4[i] = ul;
}

// ---------------------------------------------------------------------------
// Kernel 2: weight [E,K,N] f32 -> [E,N,K] bf16 hi/lo (32x32 SMEM transpose)
// ---------------------------------------------------------------------------
__global__ void k_split_weight(const float* __restrict__ w) {
    __shared__ float tile[32][33];
    int e = blockIdx.z;
    int k0 = blockIdx.x * 32;
    int n0 = blockIdx.y * 32;
    int tx = threadIdx.x, ty = threadIdx.y;   // (32, 8)
    #pragma unroll
    for (int i = 0; i < 4; i++) {
        int k = k0 + ty + 8 * i;
        tile[ty + 8 * i][tx] = w[((size_t)e * KDIM + k) * NDIM + n0 + tx];
    }
    __syncthreads();
    __nv_bfloat16* wh = (__nv_bfloat16*)d_w_hi4;
    __nv_bfloat16* wl = (__nv_bfloat16*)d_w_lo4;
    #pragma unroll
    for (int i = 0; i < 4; i++) {
        int n = n0 + ty + 8 * i;
        float v = tile[tx][ty + 8 * i];       // = w[e][k0+tx][n]
        __nv_bfloat16 h, l;
        split_bf16(v, h, l);
        size_t o = ((size_t)e * NDIM + n) * KDIM + k0 + tx;
        wh[o] = h;
        wl[o] = l;
    }
}

// ---------------------------------------------------------------------------
// Kernel 3: per-row epilogue scale + inverse scatter index + counter reset
// ---------------------------------------------------------------------------
__global__ void k_small(const int* __restrict__ splits,
                        const int* __restrict__ sidx,
                        const float* __restrict__ is,
                        const float* __restrict__ ws,
                        const float* __restrict__ ovs) {
    int m = blockIdx.x * blockDim.x + threadIdx.x;
    if (m == 0) d_tilectr = 0;                 // reset dynamic tile counter
    if (m >= MROWS) return;
    int e = 0, cum = splits[0];
    while (m >= cum && e < NEXP - 1) { e++; cum += splits[e]; }
    d_rowscale[m] = is[0] * ws[e] * ovs[m];
    d_inv[sidx[m]] = m / TOPK;     // sidx flat index m = t*TOPK + k
}

// ---------------------------------------------------------------------------
// Kernel 4: persistent grouped GEMM (3-term bf16 mma.sync, 3-stage cp.async
// ring rolling across tile boundaries, dynamic tile stealing, fused
// scale + scatter-reduce epilogue via red.global)
// ---------------------------------------------------------------------------
__device__ __forceinline__ int expert_of(const int* splits, int m0) {
    int e = 0, cum = splits[0];
    while (m0 >= cum && e < NEXP - 1) { e++; cum += splits[e]; }
    return e;
}

__device__ __forceinline__ void load_chunk(uint32_t stagebase, int ch,
                                           int tid, int m0, int n0, int e) {
    const char* aH = (const char*)d_a_hi4;
    const char* aL = (const char*)d_a_lo4;
    const char* bH = (const char*)d_w_hi4;
    const char* bL = (const char*)d_w_lo4;
    // 512 16B-chunks per tensor: row = i>>2 (128 rows), c = i&3
    #pragma unroll
    for (int rep = 0; rep < 2; rep++) {
        int i = tid + rep * 256;
        int row = i >> 2, c = i & 3;
        uint32_t soff = row * 64 + ((c ^ ((row >> 1) & 3)) << 4);
        size_t ga = ((size_t)(m0 + row) * KDIM + ch * CH_K) * 2 + c * 16;
        size_t gb = (((size_t)e * NDIM + n0 + row) * KDIM + ch * CH_K) * 2 + c * 16;
        cp_async16(stagebase + 0 * TBYTES + soff, aH + ga);
        cp_async16(stagebase + 1 * TBYTES + soff, aL + ga);
        cp_async16(stagebase + 2 * TBYTES + soff, bH + gb);
        cp_async16(stagebase + 3 * TBYTES + soff, bL + gb);
    }
}

__global__ void __launch_bounds__(256, 2)
k_moe_gemm(const int* __restrict__ splits, float* __restrict__ out) {
    extern __shared__ char smem[];
    uint32_t sbase = smem_to_u32(smem);
    volatile int* s_next = (volatile int*)(smem + NSTAGE * STAGE);
    int tid = threadIdx.x;
    int wid = tid >> 5;
    int lid = tid & 31;
    int wm = wid >> 2;        // 0..1  (64-row slab)
    int wn = wid & 3;         // 0..3  (32-col slab)

    // per-thread ldmatrix bases (swizzle term invariant under row += 16)
    int rA = wm * 64 + (lid & 15);          // + mi*16
    int cA = lid >> 4;                      // + 2*ks
    int swA = (rA >> 1) & 3;
    int g = lid >> 3, r = lid & 7;
    int rB = wn * 32 + ((g >> 1) << 3) + r; // + bi*16
    int cB = g & 1;                         // + 2*ks
    int swB = (rB >> 1) & 3;
    uint32_t baseA = (uint32_t)rA * 64;
    uint32_t baseB = (uint32_t)rB * 64;

    // first tile via dynamic counter
    if (tid == 0) s_next[0] = atomicAdd(&d_tilectr, 1);
    __syncthreads();
    int cur = s_next[0];
    if (cur >= NTILES) return;
    int m0 = (cur / NTN) * TILE_M;
    int n0 = (cur % NTN) * TILE_N;
    int e  = expert_of(splits, m0);

    float acc[4][4][4];
    #pragma unroll
    for (int mi = 0; mi < 4; mi++)
        #pragma unroll
        for (int ni = 0; ni < 4; ni++)
            #pragma unroll
            for (int q = 0; q < 4; q++) acc[mi][ni][q] = 0.f;

    uint32_t st_c = sbase, st_n = sbase + STAGE, st_p = sbase + 2 * STAGE;
    load_chunk(st_c, 0, tid, m0, n0, e); cp_commit();
    load_chunk(st_n, 1, tid, m0, n0, e); cp_commit();

    int nxt = NTILES, nm0 = 0, nn0 = 0, ne = 0;
    while (true) {
        for (int ch = 0; ch < NUM_CH; ch++) {
            cp_wait<1>();
            __syncthreads();  // all warps done reading slot st_p -> safe to fill
                              // (also publishes s_next written at ch==13)
            if (ch == 14) {
                nxt = s_next[0];
                if (nxt < NTILES) {
                    nm0 = (nxt / NTN) * TILE_M;
                    nn0 = (nxt % NTN) * TILE_N;
                    ne  = expert_of(splits, nm0);
                }
            }
            if (ch < NUM_CH - 2) {
                load_chunk(st_p, ch + 2, tid, m0, n0, e);
            } else if (nxt < NTILES) {
                load_chunk(st_p, ch - (NUM_CH - 2), tid, nm0, nn0, ne);
            }
            cp_commit();      // always commit (keeps pending-group invariant)
            if (ch == 13 && tid == 0) s_next[0] = atomicAdd(&d_tilectr, 1);

            uint32_t Ah = st_c, Al = st_c + TBYTES;
            uint32_t Bh = st_c + 2 * TBYTES, Bl = st_c + 3 * TBYTES;

            #pragma unroll
            for (int ks = 0; ks < 2; ks++) {
                uint32_t coA = (uint32_t)(((cA + 2 * ks) ^ swA) << 4);
                uint32_t coB = (uint32_t)(((cB + 2 * ks) ^ swB) << 4);
                uint32_t ah[4][4], bh[2][4];
                #pragma unroll
                for (int mi = 0; mi < 4; mi++)
                    ldm_x4(ah[mi], Ah + baseA + mi * 1024 + coA);
                #pragma unroll
                for (int bi = 0; bi < 2; bi++)
                    ldm_x4(bh[bi], Bh + baseB + bi * 1024 + coB);
                #pragma unroll
                for (int mi = 0; mi < 4; mi++)
                    #pragma unroll
                    for (int ni = 0; ni < 4; ni++)
                        mma_bf16(acc[mi][ni], ah[mi], &bh[ni >> 1][(ni & 1) * 2]);

                uint32_t al[4][4];
                #pragma unroll
                for (int mi = 0; mi < 4; mi++)
                    ldm_x4(al[mi], Al + baseA + mi * 1024 + coA);
                #pragma unroll
                for (int mi = 0; mi < 4; mi++)
                    #pragma unroll
                    for (int ni = 0; ni < 4; ni++)
                        mma_bf16(acc[mi][ni], al[mi], &bh[ni >> 1][(ni & 1) * 2]);

                uint32_t bl[2][4];
                #pragma unroll
                for (int bi = 0; bi < 2; bi++)
                    ldm_x4(bl[bi], Bl + baseB + bi * 1024 + coB);
                #pragma unroll
                for (int mi = 0; mi < 4; mi++)
                    #pragma unroll
                    for (int ni = 0; ni < 4; ni++)
                        mma_bf16(acc[mi][ni], ah[mi], &bl[ni >> 1][(ni & 1) * 2]);
            }
            // rotate stages
            uint32_t tmp = st_c; st_c = st_n; st_n = st_p; st_p = tmp;
        }

        // fused epilogue: out[inv[m]] += acc * rowscale[m]  (scatter-reduce)
        {
            int r0 = m0 + wm * 64 + (lid >> 2);
            int ncol0 = n0 + wn * 32 + (lid & 3) * 2;
            #pragma unroll
            for (int mi = 0; mi < 4; mi++) {
                int ma = r0 + mi * 16, mb = ma + 8;
                int   ta = d_inv[ma],      tb = d_inv[mb];
                float sa = d_rowscale[ma], sb = d_rowscale[mb];
                #pragma unroll
                for (int ni = 0; ni < 4; ni++) {
                    int n = ncol0 + ni * 8;
                    red_add_v2(&out[(size_t)ta * NDIM + n],
                               acc[mi][ni][0] * sa, acc[mi][ni][1] * sa);
                    red_add_v2(&out[(size_t)tb * NDIM + n],
                               acc[mi][ni][2] * sb, acc[mi][ni][3] * sb);
                }
            }
        }

        if (nxt >= NTILES) break;
        cur = nxt; m0 = nm0; n0 = nn0; e = ne;
        #pragma unroll
        for (int mi = 0; mi < 4; mi++)
            #pragma unroll
            for (int ni = 0; ni < 4; ni++)
                #pragma unroll
                for (int q = 0; q < 4; q++) acc[mi][ni][q] = 0.f;
    }
    cp_wait<0>();   // drain any in-flight groups before exit
}

// ---------------------------------------------------------------------------
// Launch
// ---------------------------------------------------------------------------
extern "C" void kernel_launch(void* const* d_in, const int* in_sizes, int n_in,
                              void* d_out, int out_size) {
    const float* inp    = (const float*)d_in[0];
    const float* weight = (const float*)d_in[1];
    const int*   splits = (const int*)d_in[2];
    const int*   sidx   = (const int*)d_in[3];
    const float* iscale = (const float*)d_in[4];
    const float* wscale = (const float*)d_in[5];
    const float* ovs    = (const float*)d_in[6];
    float* out = (float*)d_out;

    cudaFuncSetAttribute(k_moe_gemm,
                         cudaFuncAttributeMaxDynamicSharedMemorySize, SMEM_GEMM);

    k_split_input<<<(MROWS * KDIM / 8) / 256, 256>>>((const float4*)inp,
                                                     (float4*)out);
    k_split_weight<<<dim3(KDIM / 32, NDIM / 32, NEXP), dim3(32, 8)>>>(weight);
    k_small<<<(MROWS + 255) / 256, 256>>>(splits, sidx, iscale, wscale, ovs);
    k_moe_gemm<<<GRID_GEMM, 256, SMEM_GEMM>>>(splits, out);
}

// round 7
// speedup vs baseline: 1.0656x; 1.0127x over previous
#include <cuda_runtime.h>
#include <cuda_bf16.h>
#include <cstdint>

// ---------------------------------------------------------------------------
// Problem constants
// ---------------------------------------------------------------------------
#define NTOK 8192
#define TOPK 2
#define NEXP 8
#define KDIM 512
#define NDIM 1024
#define MROWS (NTOK * TOPK)   // 16384

// GEMM tiling (mma.sync path — base sm_100 target, no tcgen05 available)
#define TILE_M 128
#define TILE_N 128
#define CH_K   32                 // bf16 K elems per chunk (64 bytes/row)
#define NUM_CH (KDIM / CH_K)      // 16
#define NTILES ((MROWS / TILE_M) * (NDIM / TILE_N))   // 1024
#define NTN    (NDIM / TILE_N)    // 8
// Swizzled smem: row stride 64B, 16B chunk c stored at c ^ ((row>>1)&3)
#define TBYTES (TILE_M * 64)      // 8192 per tensor (A/B tiles are both 128 rows)
#define STAGE  (4 * TBYTES)       // Ah, Al, Bh, Bl = 32768
#define NSTAGE 3
#define SMEM_GEMM (NSTAGE * STAGE + 16)  // + broadcast slot
#define GRID_GEMM 296             // 2 persistent CTAs per SM
#define NTHREADS 128              // 4 warps, 2x2 grid of 64x64 warp tiles

// ---------------------------------------------------------------------------
// PTX helpers (base-target instructions, sm_90 or lower vintage)
// ---------------------------------------------------------------------------
__device__ __forceinline__ uint32_t smem_to_u32(const void* p) {
    uint32_t a;
    asm("{ .reg .u64 t; cvta.to.shared.u64 t, %1; cvt.u32.u64 %0, t; }"
        : "=r"(a) : "l"(p));
    return a;
}

__device__ __forceinline__ void cp_async16(uint32_t dst, const void* src) {
    asm volatile("cp.async.cg.shared.global [%0], [%1], 16;"
                 :: "r"(dst), "l"(src) : "memory");
}
__device__ __forceinline__ void cp_commit() {
    asm volatile("cp.async.commit_group;" ::: "memory");
}
template <int N>
__device__ __forceinline__ void cp_wait() {
    asm volatile("cp.async.wait_group %0;" :: "n"(N) : "memory");
}

__device__ __forceinline__ void ldm_x4(uint32_t* r, uint32_t addr) {
    asm volatile("ldmatrix.sync.aligned.m8n8.x4.shared.b16 {%0,%1,%2,%3}, [%4];"
                 : "=r"(r[0]), "=r"(r[1]), "=r"(r[2]), "=r"(r[3])
                 : "r"(addr));
}

__device__ __forceinline__ void mma_bf16(float* c, const uint32_t* a,
                                         const uint32_t* b) {
    asm volatile(
        "mma.sync.aligned.m16n8k16.row.col.f32.bf16.bf16.f32 "
        "{%0,%1,%2,%3}, {%4,%5,%6,%7}, {%8,%9}, {%0,%1,%2,%3};"
        : "+f"(c[0]), "+f"(c[1]), "+f"(c[2]), "+f"(c[3])
        : "r"(a[0]), "r"(a[1]), "r"(a[2]), "r"(a[3]), "r"(b[0]), "r"(b[1]));
}

__device__ __forceinline__ void red_add_v2(float* gaddr, float x, float y) {
    asm volatile("red.global.add.v2.f32 [%0], {%1, %2};"
                 :: "l"(gaddr), "f"(x), "f"(y) : "memory");
}

// ---------------------------------------------------------------------------
// Scratch (static __device__ — no allocation allowed)
// ---------------------------------------------------------------------------
__device__ uint4  d_a_hi4[MROWS * KDIM / 8];          // bf16 [M,K] hi (16 MB)
__device__ uint4  d_a_lo4[MROWS * KDIM / 8];          // bf16 [M,K] lo
__device__ uint4  d_w_hi4[NEXP * NDIM * KDIM / 8];    // bf16 [E,N,K] hi (8 MB)
__device__ uint4  d_w_lo4[NEXP * NDIM * KDIM / 8];    // bf16 [E,N,K] lo
__device__ float  d_rowscale[MROWS];
__device__ int    d_inv[MROWS];                       // inv[s] = token of sorted row s
__device__ int    d_tilectr;                          // dynamic tile counter

__device__ __forceinline__ void split_bf16(float x, __nv_bfloat16& h, __nv_bfloat16& l) {
    h = __float2bfloat16_rn(x);
    l = __float2bfloat16_rn(x - __bfloat162float(h));
}

// ---------------------------------------------------------------------------
// Kernel 1: split input f32 -> bf16 hi/lo, and zero the output surface
// ---------------------------------------------------------------------------
__global__ void k_split_input(const float4* __restrict__ in4,
                              float4* __restrict__ out4) {
    int i = blockIdx.x * blockDim.x + threadIdx.x;   // exactly MROWS*KDIM/8 threads
    // zero d_out: NTOK*NDIM/4 = 2*nthreads float4s
    out4[2 * i]     = make_float4(0.f, 0.f, 0.f, 0.f);
    out4[2 * i + 1] = make_float4(0.f, 0.f, 0.f, 0.f);

    float4 v0 = in4[2 * i], v1 = in4[2 * i + 1];
    __nv_bfloat16 h[8], l[8];
    split_bf16(v0.x, h[0], l[0]); split_bf16(v0.y, h[1], l[1]);
    split_bf16(v0.z, h[2], l[2]); split_bf16(v0.w, h[3], l[3]);
    split_bf16(v1.x, h[4], l[4]); split_bf16(v1.y, h[5], l[5]);
    split_bf16(v1.z, h[6], l[6]); split_bf16(v1.w, h[7], l[7]);
    uint4 uh, ul;
    __nv_bfloat162 t;
    t = __nv_bfloat162(h[0], h[1]); uh.x = *(uint32_t*)&t;
    t = __nv_bfloat162(h[2], h[3]); uh.y = *(uint32_t*)&t;
    t = __nv_bfloat162(h[4], h[5]); uh.z = *(uint32_t*)&t;
    t = __nv_bfloat162(h[6], h[7]); uh.w = *(uint32_t*)&t;
    t = __nv_bfloat162(l[0], l[1]); ul.x = *(uint32_t*)&t;
    t = __nv_bfloat162(l[2], l[3]); ul.y = *(uint32_t*)&t;
    t = __nv_bfloat162(l[4], l[5]); ul.z = *(uint32_t*)&t;
    t = __nv_bfloat162(l[6], l[7]); ul.w = *(uint32_t*)&t;
    d_a_hi4[i] = uh;
    d_a_lo4[i] = ul;
}

// ---------------------------------------------------------------------------
// Kernel 2: weight [E,K,N] f32 -> [E,N,K] bf16 hi/lo (32x32 SMEM transpose)
// ---------------------------------------------------------------------------
__global__ void k_split_weight(const float* __restrict__ w) {
    __shared__ float tile[32][33];
    int e = blockIdx.z;
    int k0 = blockIdx.x * 32;
    int n0 = blockIdx.y * 32;
    int tx = threadIdx.x, ty = threadIdx.y;   // (32, 8)
    #pragma unroll
    for (int i = 0; i < 4; i++) {
        int k = k0 + ty + 8 * i;
        tile[ty + 8 * i][tx] = w[((size_t)e * KDIM + k) * NDIM + n0 + tx];
    }
    __syncthreads();
    __nv_bfloat16* wh = (__nv_bfloat16*)d_w_hi4;
    __nv_bfloat16* wl = (__nv_bfloat16*)d_w_lo4;
    #pragma unroll
    for (int i = 0; i < 4; i++) {
        int n = n0 + ty + 8 * i;
        float v = tile[tx][ty + 8 * i];       // = w[e][k0+tx][n]
        __nv_bfloat16 h, l;
        split_bf16(v, h, l);
        size_t o = ((size_t)e * NDIM + n) * KDIM + k0 + tx;
        wh[o] = h;
        wl[o] = l;
    }
}

// ---------------------------------------------------------------------------
// Kernel 3: per-row epilogue scale + inverse scatter index + counter reset
// ---------------------------------------------------------------------------
__global__ void k_small(const int* __restrict__ splits,
                        const int* __restrict__ sidx,
                        const float* __restrict__ is,
                        const float* __restrict__ ws,
                        const float* __restrict__ ovs) {
    int m = blockIdx.x * blockDim.x + threadIdx.x;
    if (m == 0) d_tilectr = 0;                 // reset dynamic tile counter
    if (m >= MROWS) return;
    int e = 0, cum = splits[0];
    while (m >= cum && e < NEXP - 1) { e++; cum += splits[e]; }
    d_rowscale[m] = is[0] * ws[e] * ovs[m];
    d_inv[sidx[m]] = m / TOPK;     // sidx flat index m = t*TOPK + k
}

// ---------------------------------------------------------------------------
// Kernel 4: persistent grouped GEMM (3-term bf16 mma.sync, 64x64 warp tiles,
// 3-stage cp.async ring rolling across tile boundaries, dynamic tile
// stealing, fused scale + scatter-reduce epilogue via red.global)
// ---------------------------------------------------------------------------
__device__ __forceinline__ int expert_of(const int* splits, int m0) {
    int e = 0, cum = splits[0];
    while (m0 >= cum && e < NEXP - 1) { e++; cum += splits[e]; }
    return e;
}

__device__ __forceinline__ void load_chunk(uint32_t stagebase, int ch,
                                           int tid, int m0, int n0, int e) {
    const char* aH = (const char*)d_a_hi4;
    const char* aL = (const char*)d_a_lo4;
    const char* bH = (const char*)d_w_hi4;
    const char* bL = (const char*)d_w_lo4;
    // 512 16B-chunks per tensor: row = i>>2 (128 rows), c = i&3
    #pragma unroll
    for (int rep = 0; rep < 4; rep++) {
        int i = tid + rep * NTHREADS;
        int row = i >> 2, c = i & 3;
        uint32_t soff = row * 64 + ((c ^ ((row >> 1) & 3)) << 4);
        size_t ga = ((size_t)(m0 + row) * KDIM + ch * CH_K) * 2 + c * 16;
        size_t gb = (((size_t)e * NDIM + n0 + row) * KDIM + ch * CH_K) * 2 + c * 16;
        cp_async16(stagebase + 0 * TBYTES + soff, aH + ga);
        cp_async16(stagebase + 1 * TBYTES + soff, aL + ga);
        cp_async16(stagebase + 2 * TBYTES + soff, bH + gb);
        cp_async16(stagebase + 3 * TBYTES + soff, bL + gb);
    }
}

__global__ void __launch_bounds__(NTHREADS, 2)
k_moe_gemm(const int* __restrict__ splits, float* __restrict__ out) {
    extern __shared__ char smem[];
    uint32_t sbase = smem_to_u32(smem);
    volatile int* s_next = (volatile int*)(smem + NSTAGE * STAGE);
    int tid = threadIdx.x;
    int wid = tid >> 5;
    int lid = tid & 31;
    int wm = wid >> 1;        // 0..1  (64-row slab)
    int wn = wid & 1;         // 0..1  (64-col slab)

    // per-thread ldmatrix bases (swizzle term invariant under row += 16)
    int rA = wm * 64 + (lid & 15);          // + mi*16
    int cA = lid >> 4;                      // + 2*ks
    int swA = (rA >> 1) & 3;
    int g = lid >> 3, r = lid & 7;
    int rB = wn * 64 + ((g >> 1) << 3) + r; // + bi*16
    int cB = g & 1;                         // + 2*ks
    int swB = (rB >> 1) & 3;
    uint32_t baseA = (uint32_t)rA * 64;
    uint32_t baseB = (uint32_t)rB * 64;

    // first tile via dynamic counter
    if (tid == 0) s_next[0] = atomicAdd(&d_tilectr, 1);
    __syncthreads();
    int cur = s_next[0];
    if (cur >= NTILES) return;
    int m0 = (cur / NTN) * TILE_M;
    int n0 = (cur % NTN) * TILE_N;
    int e  = expert_of(splits, m0);

    float acc[4][8][4];
    #pragma unroll
    for (int mi = 0; mi < 4; mi++)
        #pragma unroll
        for (int ni = 0; ni < 8; ni++)
            #pragma unroll
            for (int q = 0; q < 4; q++) acc[mi][ni][q] = 0.f;

    uint32_t st_c = sbase, st_n = sbase + STAGE, st_p = sbase + 2 * STAGE;
    load_chunk(st_c, 0, tid, m0, n0, e); cp_commit();
    load_chunk(st_n, 1, tid, m0, n0, e); cp_commit();

    int nxt = NTILES, nm0 = 0, nn0 = 0, ne = 0;
    while (true) {
        for (int ch = 0; ch < NUM_CH; ch++) {
            cp_wait<1>();
            __syncthreads();  // all warps done reading slot st_p -> safe to fill
                              // (also publishes s_next written at ch==13)
            if (ch == 14) {
                nxt = s_next[0];
                if (nxt < NTILES) {
                    nm0 = (nxt / NTN) * TILE_M;
                    nn0 = (nxt % NTN) * TILE_N;
                    ne  = expert_of(splits, nm0);
                }
            }
            if (ch < NUM_CH - 2) {
                load_chunk(st_p, ch + 2, tid, m0, n0, e);
            } else if (nxt < NTILES) {
                load_chunk(st_p, ch - (NUM_CH - 2), tid, nm0, nn0, ne);
            }
            cp_commit();      // always commit (keeps pending-group invariant)
            if (ch == 13 && tid == 0) s_next[0] = atomicAdd(&d_tilectr, 1);

            uint32_t Ah = st_c, Al = st_c + TBYTES;
            uint32_t Bh = st_c + 2 * TBYTES, Bl = st_c + 3 * TBYTES;

            #pragma unroll
            for (int ks = 0; ks < 2; ks++) {
                uint32_t coA = (uint32_t)(((cA + 2 * ks) ^ swA) << 4);
                uint32_t coB = (uint32_t)(((cB + 2 * ks) ^ swB) << 4);
                uint32_t ah[4][4], bh[4][4];
                #pragma unroll
                for (int mi = 0; mi < 4; mi++)
                    ldm_x4(ah[mi], Ah + baseA + mi * 1024 + coA);
                #pragma unroll
                for (int bi = 0; bi < 4; bi++)
                    ldm_x4(bh[bi], Bh + baseB + bi * 1024 + coB);
                #pragma unroll
                for (int mi = 0; mi < 4; mi++)
                    #pragma unroll
                    for (int ni = 0; ni < 8; ni++)
                        mma_bf16(acc[mi][ni], ah[mi], &bh[ni >> 1][(ni & 1) * 2]);

                uint32_t al[4][4];
                #pragma unroll
                for (int mi = 0; mi < 4; mi++)
                    ldm_x4(al[mi], Al + baseA + mi * 1024 + coA);
                #pragma unroll
                for (int mi = 0; mi < 4; mi++)
                    #pragma unroll
                    for (int ni = 0; ni < 8; ni++)
                        mma_bf16(acc[mi][ni], al[mi], &bh[ni >> 1][(ni & 1) * 2]);

                uint32_t bl[4][4];
                #pragma unroll
                for (int bi = 0; bi < 4; bi++)
                    ldm_x4(bl[bi], Bl + baseB + bi * 1024 + coB);
                #pragma unroll
                for (int mi = 0; mi < 4; mi++)
                    #pragma unroll
                    for (int ni = 0; ni < 8; ni++)
                        mma_bf16(acc[mi][ni], ah[mi], &bl[ni >> 1][(ni & 1) * 2]);
            }
            // rotate stages
            uint32_t tmp = st_c; st_c = st_n; st_n = st_p; st_p = tmp;
        }

        // fused epilogue: out[inv[m]] += acc * rowscale[m]  (scatter-reduce)
        {
            int r0 = m0 + wm * 64 + (lid >> 2);
            int ncol0 = n0 + wn * 64 + (lid & 3) * 2;
            #pragma unroll
            for (int mi = 0; mi < 4; mi++) {
                int ma = r0 + mi * 16, mb = ma + 8;
                int   ta = d_inv[ma],      tb = d_inv[mb];
                float sa = d_rowscale[ma], sb = d_rowscale[mb];
                #pragma unroll
                for (int ni = 0; ni < 8; ni++) {
                    int n = ncol0 + ni * 8;
                    red_add_v2(&out[(size_t)ta * NDIM + n],
                               acc[mi][ni][0] * sa, acc[mi][ni][1] * sa);
                    red_add_v2(&out[(size_t)tb * NDIM + n],
                               acc[mi][ni][2] * sb, acc[mi][ni][3] * sb);
                }
            }
        }

        if (nxt >= NTILES) break;
        cur = nxt; m0 = nm0; n0 = nn0; e = ne;
        #pragma unroll
        for (int mi = 0; mi < 4; mi++)
            #pragma unroll
            for (int ni = 0; ni < 8; ni++)
                #pragma unroll
                for (int q = 0; q < 4; q++) acc[mi][ni][q] = 0.f;
    }
    cp_wait<0>();   // drain any in-flight groups before exit
}

// ---------------------------------------------------------------------------
// Launch
// ---------------------------------------------------------------------------
extern "C" void kernel_launch(void* const* d_in, const int* in_sizes, int n_in,
                              void* d_out, int out_size) {
    const float* inp    = (const float*)d_in[0];
    const float* weight = (const float*)d_in[1];
    const int*   splits = (const int*)d_in[2];
    const int*   sidx   = (const int*)d_in[3];
    const float* iscale = (const float*)d_in[4];
    const float* wscale = (const float*)d_in[5];
    const float* ovs    = (const float*)d_in[6];
    float* out = (float*)d_out;

    cudaFuncSetAttribute(k_moe_gemm,
                         cudaFuncAttributeMaxDynamicSharedMemorySize, SMEM_GEMM);

    k_split_input<<<(MROWS * KDIM / 8) / 256, 256>>>((const float4*)inp,
                                                     (float4*)out);
    k_split_weight<<<dim3(KDIM / 32, NDIM / 32, NEXP), dim3(32, 8)>>>(weight);
    k_small<<<(MROWS + 255) / 256, 256>>>(splits, sidx, iscale, wscale, ovs);
    k_moe_gemm<<<GRID_GEMM, NTHREADS, SMEM_GEMM>>>(splits, out);
}

// round 9
// speedup vs baseline: 1.3525x; 1.2692x over previous
#include <cuda_runtime.h>
#include <cuda_bf16.h>
#include <cstdint>

#define NTOK 8192
#define TOPK 2
#define NEXP 8
#define KDIM 512
#define NDIM 1024
#define MROWS (NTOK * TOPK)

#define TILE_M 128
#define TILE_N 128
#define CH_K   32
#define NUM_CH (KDIM / CH_K)
#define NTILES ((MROWS / TILE_M) * (NDIM / TILE_N))
#define NTN    (NDIM / TILE_N)
#define TBYTES (TILE_M * 128)
#define STAGE  (2 * TBYTES)
#define NSTAGE 3
#define SMEM_GEMM (NSTAGE * STAGE + 16)
#define GRID_GEMM 296
#define NTHREADS 128

__device__ __forceinline__ uint32_t smem_to_u32(const void* p) {
    uint32_t a;
    asm("{ .reg .u64 t; cvta.to.shared.u64 t, %1; cvt.u32.u64 %0, t; }"
        : "=r"(a) : "l"(p));
    return a;
}
__device__ __forceinline__ void cp_async16(uint32_t dst, const void* src) {
    asm volatile("cp.async.cg.shared.global [%0], [%1], 16;"
                 :: "r"(dst), "l"(src) : "memory");
}
__device__ __forceinline__ void cp_commit() {
    asm volatile("cp.async.commit_group;" ::: "memory");
}
template <int N>
__device__ __forceinline__ void cp_wait() {
    asm volatile("cp.async.wait_group %0;" :: "n"(N) : "memory");
}
__device__ __forceinline__ void ldm_x4(uint32_t* r, uint32_t addr) {
    asm volatile("ldmatrix.sync.aligned.m8n8.x4.shared.b16 {%0,%1,%2,%3}, [%4];"
                 : "=r"(r[0]), "=r"(r[1]), "=r"(r[2]), "=r"(r[3])
                 : "r"(addr));
}
__device__ __forceinline__ void mma_tf32(float* c, const uint32_t* a,
                                         const uint32_t* b) {
    asm volatile(
        "mma.sync.aligned.m16n8k8.row.col.f32.tf32.tf32.f32 "
        "{%0,%1,%2,%3}, {%4,%5,%6,%7}, {%8,%9}, {%0,%1,%2,%3};"
        : "+f"(c[0]), "+f"(c[1]), "+f"(c[2]), "+f"(c[3])
        : "r"(a[0]), "r"(a[1]), "r"(a[2]), "r"(a[3]), "r"(b[0]), "r"(b[1]));
}
__device__ __forceinline__ uint32_t f32_to_tf32(float f) {
    uint32_t o;
    asm("cvt.rna.tf32.f32 %0, %1;" : "=r"(o) : "f"(f));
    return o;
}
__device__ __forceinline__ void red_add_v2(float* gaddr, float x, float y) {
    asm volatile("red.global.add.v2.f32 [%0], {%1, %2};"
                 :: "l"(gaddr), "f"(x), "f"(y) : "memory");
}

__device__ uint4  d_a_t4[MROWS * KDIM / 4];           // tf32 [M,K]   (32 MB)
__device__ uint4  d_w_t4[NEXP * NDIM * KDIM / 4];     // tf32 [E,N,K] (32 MB)
__device__ float  d_rowscale[MROWS];
__device__ int    d_inv[MROWS];
__device__ int    d_tilectr;

// ---------------------------------------------------------------------------
// Kernel 1: convert input f32 -> tf32 (RN) + zero output surface
// ---------------------------------------------------------------------------
__global__ void k_split_input(const float4* __restrict__ in4,
                              float4* __restrict__ out4) {
    int i = blockIdx.x * blockDim.x + threadIdx.x;
    out4[2 * i]     = make_float4(0.f, 0.f, 0.f, 0.f);
    out4[2 * i + 1] = make_float4(0.f, 0.f, 0.f, 0.f);
    float4 v0 = in4[2 * i], v1 = in4[2 * i + 1];
    uint4 t0, t1;
    t0.x = f32_to_tf32(v0.x); t0.y = f32_to_tf32(v0.y);
    t0.z = f32_to_tf32(v0.z); t0.w = f32_to_tf32(v0.w);
    t1.x = f32_to_tf32(v1.x); t1.y = f32_to_tf32(v1.y);
    t1.z = f32_to_tf32(v1.z); t1.w = f32_to_tf32(v1.w);
    d_a_t4[2 * i]     = t0;
    d_a_t4[2 * i + 1] = t1;
}

// ---------------------------------------------------------------------------
// Kernel 2: weight [E,K,N] f32 -> [E,N,K] tf32 (32x32 SMEM transpose)
// ---------------------------------------------------------------------------
__global__ void k_split_weight(const float* __restrict__ w) {
    __shared__ float tile[32][33];
    int e = blockIdx.z;
    int k0 = blockIdx.x * 32;
    int n0 = blockIdx.y * 32;
    int tx = threadIdx.x, ty = threadIdx.y;
    #pragma unroll
    for (int i = 0; i < 4; i++) {
        int k = k0 + ty + 8 * i;
        tile[ty + 8 * i][tx] = w[((size_t)e * KDIM + k) * NDIM + n0 + tx];
    }
    __syncthreads();
    uint32_t* wt = (uint32_t*)d_w_t4;
    #pragma unroll
    for (int i = 0; i < 4; i++) {
        int n = n0 + ty + 8 * i;
        float v = tile[tx][ty + 8 * i];
        size_t o = ((size_t)e * NDIM + n) * KDIM + k0 + tx;
        wt[o] = f32_to_tf32(v);
    }
}

// ---------------------------------------------------------------------------
// Kernel 3: per-row epilogue scale + inverse scatter index + counter reset
// ---------------------------------------------------------------------------
__global__ void k_small(const int* __restrict__ splits,
                        const int* __restrict__ sidx,
                        const float* __restrict__ is,
                        const float* __restrict__ ws,
                        const float* __restrict__ ovs) {
    int m = blockIdx.x * blockDim.x + threadIdx.x;
    if (m == 0) d_tilectr = 0;
    if (m >= MROWS) return;
    int e = 0, cum = splits[0];
    while (m >= cum && e < NEXP - 1) { e++; cum += splits[e]; }
    d_rowscale[m] = is[0] * ws[e] * ovs[m];
    d_inv[sidx[m]] = m / TOPK;
}

__device__ __forceinline__ int expert_of(const int* splits, int m0) {
    int e = 0, cum = splits[0];
    while (m0 >= cum && e < NEXP - 1) { e++; cum += splits[e]; }
    return e;
}

__device__ __forceinline__ void load_chunk(uint32_t stagebase, int ch,
                                           int tid, int m0, int n0, int e) {
    const char* aT = (const char*)d_a_t4;
    const char* bT = (const char*)d_w_t4;
    // 1024 16B-chunks per tensor: row = i>>3 (128 rows), c = i&7 (8 x 16B)
    #pragma unroll
    for (int rep = 0; rep < 8; rep++) {
        int i = tid + rep * NTHREADS;
        int row = i >> 3, c = i & 7;
        uint32_t soff = row * 128 + ((c ^ (row & 7)) << 4);
        size_t ga = ((size_t)(m0 + row) * KDIM + ch * CH_K) * 4 + c * 16;
        size_t gb = (((size_t)e * NDIM + n0 + row) * KDIM + ch * CH_K) * 4 + c * 16;
        cp_async16(stagebase + soff, aT + ga);
        cp_async16(stagebase + TBYTES + soff, bT + gb);
    }
}

// ---------------------------------------------------------------------------
// Kernel 4: persistent grouped GEMM (single-pass tf32 mma m16n8k8, 64x64
// warp tiles, 3-stage cp.async ring rolling across tile boundaries, dynamic
// tile stealing, fused scale + scatter-reduce epilogue via red.global)
// ---------------------------------------------------------------------------
__global__ void __launch_bounds__(NTHREADS, 2)
k_moe_gemm(const int* __restrict__ splits, float* __restrict__ out) {
    extern __shared__ char smem[];
    uint32_t sbase = smem_to_u32(smem);
    volatile int* s_next = (volatile int*)(smem + NSTAGE * STAGE);
    int tid = threadIdx.x;
    int wid = tid >> 5;
    int lid = tid & 31;
    int wm = wid >> 1;        // 0..1  (64-row slab)
    int wn = wid & 1;         // 0..1  (64-col slab)

    // A lanes: tile groups {r0-7,k0},{r8-15,k0},{r0-7,k1},{r8-15,k1}
    int rA = wm * 64 + (lid & 15);          // + mi*16
    int cA = lid >> 4;                      // 16B-chunk, + 2*ks
    int sA = lid & 7;                       // swizzle term (row & 7)
    // B lanes: tile groups {n0-7,k0},{n0-7,k1},{n8-15,k0},{n8-15,k1}
    int rB = wn * 64 + (lid & 7) + ((lid >> 4) & 1) * 8;   // + bp*16
    int cB = (lid >> 3) & 1;                // + 2*ks
    int sB = lid & 7;
    uint32_t baseA = (uint32_t)rA * 128;
    uint32_t baseB = (uint32_t)rB * 128;

    if (tid == 0) s_next[0] = atomicAdd(&d_tilectr, 1);
    __syncthreads();
    int cur = s_next[0];
    if (cur >= NTILES) return;
    int m0 = (cur / NTN) * TILE_M;
    int n0 = (cur % NTN) * TILE_N;
    int e  = expert_of(splits, m0);

    float acc[4][8][4];
    #pragma unroll
    for (int mi = 0; mi < 4; mi++)
        #pragma unroll
        for (int ni = 0; ni < 8; ni++)
            #pragma unroll
            for (int q = 0; q < 4; q++) acc[mi][ni][q] = 0.f;

    uint32_t st_c = sbase, st_n = sbase + STAGE, st_p = sbase + 2 * STAGE;
    load_chunk(st_c, 0, tid, m0, n0, e); cp_commit();
    load_chunk(st_n, 1, tid, m0, n0, e); cp_commit();

    int nxt = NTILES, nm0 = 0, nn0 = 0, ne = 0;
    while (true) {
        for (int ch = 0; ch < NUM_CH; ch++) {
            cp_wait<1>();
            __syncthreads();  // all warps done with slot st_p -> safe to refill
            if (ch == 14) {
                nxt = s_next[0];
                if (nxt < NTILES) {
                    nm0 = (nxt / NTN) * TILE_M;
                    nn0 = (nxt % NTN) * TILE_N;
                    ne  = expert_of(splits, nm0);
                }
            }
            if (ch < NUM_CH - 2) {
                load_chunk(st_p, ch + 2, tid, m0, n0, e);
            } else if (nxt < NTILES) {
                load_chunk(st_p, ch - (NUM_CH - 2), tid, nm0, nn0, ne);
            }
            cp_commit();
            if (ch == 13 && tid == 0) s_next[0] = atomicAdd(&d_tilectr, 1);

            uint32_t A = st_c, B = st_c + TBYTES;

            #pragma unroll
            for (int ks = 0; ks < 4; ks++) {   // 4 k8-steps per 32-K chunk
                uint32_t coA = (uint32_t)(((cA + 2 * ks) ^ sA) << 4);
                uint32_t coB = (uint32_t)(((cB + 2 * ks) ^ sB) << 4);
                uint32_t a[4][4], b[4][4];
                #pragma unroll
                for (int mi = 0; mi < 4; mi++)
                    ldm_x4(a[mi], A + baseA + mi * 2048 + coA);
                #pragma unroll
                for (int bp = 0; bp < 4; bp++)
                    ldm_x4(b[bp], B + baseB + bp * 2048 + coB);
                // b[bp]: regs 0,1 = n-rows bp*16+0-7 (k0-3, k4-7);
                //        regs 2,3 = n-rows bp*16+8-15 (k0-3, k4-7)
                #pragma unroll
                for (int mi = 0; mi < 4; mi++)
                    #pragma unroll
                    for (int ni = 0; ni < 8; ni++)
                        mma_tf32(acc[mi][ni], a[mi], &b[ni >> 1][(ni & 1) * 2]);
            }
            uint32_t tmp = st_c; st_c = st_n; st_n = st_p; st_p = tmp;
        }

        // fused epilogue: out[inv[m]] += acc * rowscale[m]  (scatter-reduce)
        {
            int r0 = m0 + wm * 64 + (lid >> 2);
            int ncol0 = n0 + wn * 64 + (lid & 3) * 2;
            #pragma unroll
            for (int mi = 0; mi < 4; mi++) {
                int ma = r0 + mi * 16, mb = ma + 8;
                int   ta = d_inv[ma],      tb = d_inv[mb];
                float sa = d_rowscale[ma], sb = d_rowscale[mb];
                #pragma unroll
                for (int ni = 0; ni < 8; ni++) {
                    int n = ncol0 + ni * 8;
                    red_add_v2(&out[(size_t)ta * NDIM + n],
                               acc[mi][ni][0] * sa, acc[mi][ni][1] * sa);
                    red_add_v2(&out[(size_t)tb * NDIM + n],
                               acc[mi][ni][2] * sb, acc[mi][ni][3] * sb);
                }
            }
        }

        if (nxt >= NTILES) break;
        cur = nxt; m0 = nm0; n0 = nn0; e = ne;
        #pragma unroll
        for (int mi = 0; mi < 4; mi++)
            #pragma unroll
            for (int ni = 0; ni < 8; ni++)
                #pragma unroll
                for (int q = 0; q < 4; q++) acc[mi][ni][q] = 0.f;
    }
    cp_wait<0>();   // drain in-flight groups before exit
}

extern "C" void kernel_launch(void* const* d_in, const int* in_sizes, int n_in,
                              void* d_out, int out_size) {
    const float* inp    = (const float*)d_in[0];
    const float* weight = (const float*)d_in[1];
    const int*   splits = (const int*)d_in[2];
    const int*   sidx   = (const int*)d_in[3];
    const float* iscale = (const float*)d_in[4];
    const float* wscale = (const float*)d_in[5];
    const float* ovs    = (const float*)d_in[6];
    float* out = (float*)d_out;

    cudaFuncSetAttribute(k_moe_gemm,
                         cudaFuncAttributeMaxDynamicSharedMemorySize, SMEM_GEMM);

    k_split_input<<<(MROWS * KDIM / 8) / 256, 256>>>((const float4*)inp,
                                                     (float4*)out);
    k_split_weight<<<dim3(KDIM / 32, NDIM / 32, NEXP), dim3(32, 8)>>>(weight);
    k_small<<<(MROWS + 255) / 256, 256>>>(splits, sidx, iscale, wscale, ovs);
    k_moe_gemm<<<GRID_GEMM, NTHREADS, SMEM_GEMM>>>(splits, out);
}